// round 1
// baseline (speedup 1.0000x reference)
#include <cuda_runtime.h>
#include <cstdint>
#include <math.h>

#define BATCH 8192
#define IN_F  1024
#define OUT_F 1024
#define DEG   5
#define NBLK  7                 // 6 jacobi polys + silu
#define KDIM  (NBLK * IN_F)     // 7168

// ------------------------ scratch (static device memory; no allocs) -------
__device__ float g_F[(size_t)BATCH * KDIM];   // feature matrix, tf32-rounded
__device__ float g_W[(size_t)OUT_F * KDIM];   // packed weights, tf32-rounded

__device__ __forceinline__ float to_tf32(float x) {
    float r;
    asm("cvt.rna.tf32.f32 %0, %1;\n" : "=f"(r) : "f"(x));
    return r;
}

// ------------------------ kernel 1: pack W' -------------------------------
// W'[o, j*IN_F + i] = coeffs[o,i,j] (j<6) ; base_weight[o,i] (j==6)
__global__ void pack_w_kernel(const float* __restrict__ bw,
                              const float* __restrict__ jc) {
    int idx = blockIdx.x * blockDim.x + threadIdx.x;
    if (idx >= OUT_F * KDIM) return;
    int o = idx / KDIM;
    int r = idx - o * KDIM;
    int j = r / IN_F;
    int i = r - j * IN_F;
    float v;
    if (j == 6) v = bw[o * IN_F + i];
    else        v = jc[(o * IN_F + i) * (DEG + 1) + j];
    g_W[idx] = to_tf32(v);
}

// ------------------------ kernel 2: features ------------------------------
// F[b, j*IN_F + i] = P_j(tanh(x[b,i])) for j<6 ; silu(x[b,i]) for j==6
__global__ void features_kernel(const float* __restrict__ x) {
    int idx = blockIdx.x * blockDim.x + threadIdx.x;
    if (idx >= BATCH * IN_F) return;
    int b = idx / IN_F;
    int i = idx - b * IN_F;

    float xv = x[idx];
    float t  = tanhf(xv);
    float sg = 1.0f / (1.0f + __expf(-xv));
    float silu = xv * sg;

    const float Aa = 1.0f, Bb = 1.0f;
    float P[DEG + 1];
    P[0] = 1.0f;
    P[1] = 0.5f * (2.0f * (Aa + 1.0f) * t + (Aa - Bb));
#pragma unroll
    for (int k = 2; k <= DEG; k++) {
        float fk = (float)k;
        float alpha = 2.0f * fk * (fk + Aa + Bb) * (2.0f * fk + Aa + Bb - 2.0f);
        float beta  = (2.0f * fk + Aa + Bb - 1.0f) * (Aa * Aa - Bb * Bb);
        float gamma = (2.0f * fk + Aa + Bb - 2.0f) * (2.0f * fk + Aa + Bb - 1.0f) * (2.0f * fk + Aa + Bb);
        float delta = 2.0f * (fk + Aa - 1.0f) * (fk + Bb - 1.0f) * (2.0f * fk + Aa + Bb);
        float Ac = (beta + alpha * t) / gamma;
        float Bc = delta / gamma;
        P[k] = Ac * P[k - 1] - Bc * P[k - 2];
    }

    float* Fr = g_F + (size_t)b * KDIM;
#pragma unroll
    for (int j = 0; j <= DEG; j++)
        Fr[j * IN_F + i] = to_tf32(P[j]);
    Fr[6 * IN_F + i] = to_tf32(silu);
}

// ------------------------ kernel 3: TF32 GEMM -----------------------------
// out[b,o] = sum_k F[b,k] * W'[o,k] + bias[o]
// Tiles: BM=128, BN=128, BK=16, 2-stage cp.async double buffer, 256 threads.
#define BM 128
#define BN 128
#define BK 16
#define PAD 4
#define BKP (BK + PAD)   // 20 floats per smem row
#define STAGES 2

__device__ __forceinline__ void cp_async16(float* smem_ptr, const float* gptr) {
    uint32_t s = (uint32_t)__cvta_generic_to_shared(smem_ptr);
    asm volatile("cp.async.cg.shared.global [%0], [%1], 16;\n" :: "r"(s), "l"(gptr));
}
__device__ __forceinline__ void cp_commit() {
    asm volatile("cp.async.commit_group;\n");
}
__device__ __forceinline__ void cp_wait1() {
    asm volatile("cp.async.wait_group 1;\n");
}
__device__ __forceinline__ void cp_wait0() {
    asm volatile("cp.async.wait_group 0;\n");
}

__device__ __forceinline__ void mma_tf32(float c[4], const float a[4], const float b[2]) {
    asm volatile(
        "mma.sync.aligned.m16n8k8.row.col.f32.tf32.tf32.f32 "
        "{%0,%1,%2,%3}, {%4,%5,%6,%7}, {%8,%9}, {%0,%1,%2,%3};\n"
        : "+f"(c[0]), "+f"(c[1]), "+f"(c[2]), "+f"(c[3])
        : "r"(__float_as_uint(a[0])), "r"(__float_as_uint(a[1])),
          "r"(__float_as_uint(a[2])), "r"(__float_as_uint(a[3])),
          "r"(__float_as_uint(b[0])), "r"(__float_as_uint(b[1])));
}

__global__ void __launch_bounds__(256, 2) gemm_kernel(const float* __restrict__ bias,
                                                      float* __restrict__ out) {
    __shared__ float As[STAGES][BM][BKP];   // 2*128*20*4 = 20480 B
    __shared__ float Bs[STAGES][BN][BKP];   // 20480 B  -> total 40 KB

    const int tid  = threadIdx.x;
    const int lane = tid & 31;
    const int warp = tid >> 5;
    const int wm   = warp & 1;   // 2 warp rows (64 each)
    const int wn   = warp >> 1;  // 4 warp cols (32 each)
    const int g    = lane >> 2;  // group id 0..7
    const int q    = lane & 3;   // thread in group 0..3

    const int bn = blockIdx.x;   // output-feature tile
    const int bm = blockIdx.y;   // batch tile

    const float* Ag = g_F + (size_t)(bm * BM) * KDIM;
    const float* Bg = g_W + (size_t)(bn * BN) * KDIM;

    float acc[4][4][4];
#pragma unroll
    for (int mf = 0; mf < 4; mf++)
#pragma unroll
        for (int nf = 0; nf < 4; nf++)
#pragma unroll
            for (int r = 0; r < 4; r++) acc[mf][nf][r] = 0.0f;

    const int KT = KDIM / BK;   // 448

    // ---- tile loader: 512 float4 chunks per tile, 256 threads, 2 each ----
    auto load_tiles = [&](int kt, int s) {
#pragma unroll
        for (int c = 0; c < 2; c++) {
            int chunk = tid + c * 256;
            int row = chunk >> 2;      // 4 chunks per 16-float row
            int c4  = chunk & 3;
            cp_async16(&As[s][row][c4 * 4], Ag + (size_t)row * KDIM + kt * BK + c4 * 4);
        }
#pragma unroll
        for (int c = 0; c < 2; c++) {
            int chunk = tid + c * 256;
            int row = chunk >> 2;
            int c4  = chunk & 3;
            cp_async16(&Bs[s][row][c4 * 4], Bg + (size_t)row * KDIM + kt * BK + c4 * 4);
        }
    };

    load_tiles(0, 0);
    cp_commit();

#pragma unroll 1
    for (int kt = 0; kt < KT; kt++) {
        if (kt + 1 < KT) {
            load_tiles(kt + 1, (kt + 1) & 1);
            cp_commit();
            cp_wait1();
        } else {
            cp_wait0();
        }
        __syncthreads();

        const int s = kt & 1;
#pragma unroll
        for (int kk = 0; kk < BK / 8; kk++) {
            const int k0 = kk * 8;
            float a[4][4];
            float b[4][2];
#pragma unroll
            for (int mf = 0; mf < 4; mf++) {
                int row = wm * 64 + mf * 16 + g;
                a[mf][0] = As[s][row][k0 + q];
                a[mf][1] = As[s][row + 8][k0 + q];
                a[mf][2] = As[s][row][k0 + q + 4];
                a[mf][3] = As[s][row + 8][k0 + q + 4];
            }
#pragma unroll
            for (int nf = 0; nf < 4; nf++) {
                int col = wn * 32 + nf * 8 + g;
                b[nf][0] = Bs[s][col][k0 + q];
                b[nf][1] = Bs[s][col][k0 + q + 4];
            }
#pragma unroll
            for (int mf = 0; mf < 4; mf++)
#pragma unroll
                for (int nf = 0; nf < 4; nf++)
                    mma_tf32(acc[mf][nf], a[mf], b[nf]);
        }
        __syncthreads();
    }

    // ---- epilogue: add bias, store float2 pairs ----
#pragma unroll
    for (int mf = 0; mf < 4; mf++) {
        int row0 = bm * BM + wm * 64 + mf * 16 + g;
#pragma unroll
        for (int nf = 0; nf < 4; nf++) {
            int col = bn * BN + wn * 32 + nf * 8 + q * 2;
            float b0 = __ldg(&bias[col]);
            float b1 = __ldg(&bias[col + 1]);
            float2 v0 = make_float2(acc[mf][nf][0] + b0, acc[mf][nf][1] + b1);
            float2 v1 = make_float2(acc[mf][nf][2] + b0, acc[mf][nf][3] + b1);
            *reinterpret_cast<float2*>(out + (size_t)row0 * OUT_F + col)       = v0;
            *reinterpret_cast<float2*>(out + (size_t)(row0 + 8) * OUT_F + col) = v1;
        }
    }
}

// ------------------------ launch ------------------------------------------
extern "C" void kernel_launch(void* const* d_in, const int* in_sizes, int n_in,
                              void* d_out, int out_size) {
    (void)in_sizes; (void)n_in; (void)out_size;
    const float* x    = (const float*)d_in[0];
    const float* bw   = (const float*)d_in[1];
    const float* jc   = (const float*)d_in[2];
    const float* bias = (const float*)d_in[3];
    float* out = (float*)d_out;

    {
        int n = OUT_F * KDIM;
        pack_w_kernel<<<(n + 255) / 256, 256>>>(bw, jc);
    }
    {
        int n = BATCH * IN_F;
        features_kernel<<<(n + 255) / 256, 256>>>(x);
    }
    {
        dim3 grid(OUT_F / BN, BATCH / BM);   // (8, 64)
        gemm_kernel<<<grid, 256>>>(bias, out);
    }
}

// round 2
// speedup vs baseline: 1.0000x; 1.0000x over previous
#include <cuda_runtime.h>
#include <cstdint>
#include <math.h>

#define BATCH 8192
#define IN_F  1024
#define OUT_F 1024
#define DEG   5
#define NBLK  7                 // 6 jacobi polys + silu
#define KDIM  (NBLK * IN_F)     // 7168

// ------------------------ scratch (static device memory; no allocs) -------
__device__ float g_F[(size_t)BATCH * KDIM];   // feature matrix, tf32-rounded
__device__ float g_W[(size_t)OUT_F * KDIM];   // packed weights, tf32-rounded

__device__ __forceinline__ float to_tf32(float x) {
    float r;
    asm("cvt.rna.tf32.f32 %0, %1;\n" : "=f"(r) : "f"(x));
    return r;
}

// ------------------------ kernel 1: pack W' -------------------------------
// W'[o, j*IN_F + i] = coeffs[o,i,j] (j<6) ; base_weight[o,i] (j==6)
__global__ void pack_w_kernel(const float* __restrict__ bw,
                              const float* __restrict__ jc) {
    int idx = blockIdx.x * blockDim.x + threadIdx.x;
    if (idx >= OUT_F * KDIM) return;
    int o = idx / KDIM;
    int r = idx - o * KDIM;
    int j = r / IN_F;
    int i = r - j * IN_F;
    float v;
    if (j == 6) v = bw[o * IN_F + i];
    else        v = jc[(o * IN_F + i) * (DEG + 1) + j];
    g_W[idx] = to_tf32(v);
}

// ------------------------ kernel 2: features ------------------------------
// F[b, j*IN_F + i] = P_j(tanh(x[b,i])) for j<6 ; silu(x[b,i]) for j==6
__global__ void features_kernel(const float* __restrict__ x) {
    int idx = blockIdx.x * blockDim.x + threadIdx.x;
    if (idx >= BATCH * IN_F) return;
    int b = idx / IN_F;
    int i = idx - b * IN_F;

    float xv = x[idx];
    float t  = tanhf(xv);
    float sg = 1.0f / (1.0f + __expf(-xv));
    float silu = xv * sg;

    const float Aa = 1.0f, Bb = 1.0f;
    float P[DEG + 1];
    P[0] = 1.0f;
    P[1] = 0.5f * (2.0f * (Aa + 1.0f) * t + (Aa - Bb));
#pragma unroll
    for (int k = 2; k <= DEG; k++) {
        float fk = (float)k;
        float alpha = 2.0f * fk * (fk + Aa + Bb) * (2.0f * fk + Aa + Bb - 2.0f);
        float beta  = (2.0f * fk + Aa + Bb - 1.0f) * (Aa * Aa - Bb * Bb);
        float gamma = (2.0f * fk + Aa + Bb - 2.0f) * (2.0f * fk + Aa + Bb - 1.0f) * (2.0f * fk + Aa + Bb);
        float delta = 2.0f * (fk + Aa - 1.0f) * (fk + Bb - 1.0f) * (2.0f * fk + Aa + Bb);
        float Ac = (beta + alpha * t) / gamma;
        float Bc = delta / gamma;
        P[k] = Ac * P[k - 1] - Bc * P[k - 2];
    }

    float* Fr = g_F + (size_t)b * KDIM;
#pragma unroll
    for (int j = 0; j <= DEG; j++)
        Fr[j * IN_F + i] = to_tf32(P[j]);
    Fr[6 * IN_F + i] = to_tf32(silu);
}

// ------------------------ kernel 3: TF32 GEMM -----------------------------
// out[b,o] = sum_k F[b,k] * W'[o,k] + bias[o]
// Tiles: BM=128, BN=128, BK=16, 2-stage cp.async double buffer, 256 threads.
#define BM 128
#define BN 128
#define BK 16
#define PAD 4
#define BKP (BK + PAD)   // 20 floats per smem row
#define STAGES 2

__device__ __forceinline__ void cp_async16(float* smem_ptr, const float* gptr) {
    uint32_t s = (uint32_t)__cvta_generic_to_shared(smem_ptr);
    asm volatile("cp.async.cg.shared.global [%0], [%1], 16;\n" :: "r"(s), "l"(gptr));
}
__device__ __forceinline__ void cp_commit() {
    asm volatile("cp.async.commit_group;\n");
}
__device__ __forceinline__ void cp_wait1() {
    asm volatile("cp.async.wait_group 1;\n");
}
__device__ __forceinline__ void cp_wait0() {
    asm volatile("cp.async.wait_group 0;\n");
}

__device__ __forceinline__ void mma_tf32(float c[4], const float a[4], const float b[2]) {
    asm volatile(
        "mma.sync.aligned.m16n8k8.row.col.f32.tf32.tf32.f32 "
        "{%0,%1,%2,%3}, {%4,%5,%6,%7}, {%8,%9}, {%0,%1,%2,%3};\n"
        : "+f"(c[0]), "+f"(c[1]), "+f"(c[2]), "+f"(c[3])
        : "r"(__float_as_uint(a[0])), "r"(__float_as_uint(a[1])),
          "r"(__float_as_uint(a[2])), "r"(__float_as_uint(a[3])),
          "r"(__float_as_uint(b[0])), "r"(__float_as_uint(b[1])));
}

__global__ void __launch_bounds__(256, 2) gemm_kernel(const float* __restrict__ bias,
                                                      float* __restrict__ out) {
    __shared__ float As[STAGES][BM][BKP];   // 2*128*20*4 = 20480 B
    __shared__ float Bs[STAGES][BN][BKP];   // 20480 B  -> total 40 KB

    const int tid  = threadIdx.x;
    const int lane = tid & 31;
    const int warp = tid >> 5;
    const int wm   = warp & 1;   // 2 warp rows (64 each)
    const int wn   = warp >> 1;  // 4 warp cols (32 each)
    const int g    = lane >> 2;  // group id 0..7
    const int q    = lane & 3;   // thread in group 0..3

    const int bn = blockIdx.x;   // output-feature tile
    const int bm = blockIdx.y;   // batch tile

    const float* Ag = g_F + (size_t)(bm * BM) * KDIM;
    const float* Bg = g_W + (size_t)(bn * BN) * KDIM;

    float acc[4][4][4];
#pragma unroll
    for (int mf = 0; mf < 4; mf++)
#pragma unroll
        for (int nf = 0; nf < 4; nf++)
#pragma unroll
            for (int r = 0; r < 4; r++) acc[mf][nf][r] = 0.0f;

    const int KT = KDIM / BK;   // 448

    // ---- tile loader: 512 float4 chunks per tile, 256 threads, 2 each ----
    auto load_tiles = [&](int kt, int s) {
#pragma unroll
        for (int c = 0; c < 2; c++) {
            int chunk = tid + c * 256;
            int row = chunk >> 2;      // 4 chunks per 16-float row
            int c4  = chunk & 3;
            cp_async16(&As[s][row][c4 * 4], Ag + (size_t)row * KDIM + kt * BK + c4 * 4);
        }
#pragma unroll
        for (int c = 0; c < 2; c++) {
            int chunk = tid + c * 256;
            int row = chunk >> 2;
            int c4  = chunk & 3;
            cp_async16(&Bs[s][row][c4 * 4], Bg + (size_t)row * KDIM + kt * BK + c4 * 4);
        }
    };

    load_tiles(0, 0);
    cp_commit();

#pragma unroll 1
    for (int kt = 0; kt < KT; kt++) {
        if (kt + 1 < KT) {
            load_tiles(kt + 1, (kt + 1) & 1);
            cp_commit();
            cp_wait1();
        } else {
            cp_wait0();
        }
        __syncthreads();

        const int s = kt & 1;
#pragma unroll
        for (int kk = 0; kk < BK / 8; kk++) {
            const int k0 = kk * 8;
            float a[4][4];
            float b[4][2];
#pragma unroll
            for (int mf = 0; mf < 4; mf++) {
                int row = wm * 64 + mf * 16 + g;
                a[mf][0] = As[s][row][k0 + q];
                a[mf][1] = As[s][row + 8][k0 + q];
                a[mf][2] = As[s][row][k0 + q + 4];
                a[mf][3] = As[s][row + 8][k0 + q + 4];
            }
#pragma unroll
            for (int nf = 0; nf < 4; nf++) {
                int col = wn * 32 + nf * 8 + g;
                b[nf][0] = Bs[s][col][k0 + q];
                b[nf][1] = Bs[s][col][k0 + q + 4];
            }
#pragma unroll
            for (int mf = 0; mf < 4; mf++)
#pragma unroll
                for (int nf = 0; nf < 4; nf++)
                    mma_tf32(acc[mf][nf], a[mf], b[nf]);
        }
        __syncthreads();
    }

    // ---- epilogue: add bias, store float2 pairs ----
#pragma unroll
    for (int mf = 0; mf < 4; mf++) {
        int row0 = bm * BM + wm * 64 + mf * 16 + g;
#pragma unroll
        for (int nf = 0; nf < 4; nf++) {
            int col = bn * BN + wn * 32 + nf * 8 + q * 2;
            float b0 = __ldg(&bias[col]);
            float b1 = __ldg(&bias[col + 1]);
            float2 v0 = make_float2(acc[mf][nf][0] + b0, acc[mf][nf][1] + b1);
            float2 v1 = make_float2(acc[mf][nf][2] + b0, acc[mf][nf][3] + b1);
            *reinterpret_cast<float2*>(out + (size_t)row0 * OUT_F + col)       = v0;
            *reinterpret_cast<float2*>(out + (size_t)(row0 + 8) * OUT_F + col) = v1;
        }
    }
}

// ------------------------ launch ------------------------------------------
extern "C" void kernel_launch(void* const* d_in, const int* in_sizes, int n_in,
                              void* d_out, int out_size) {
    (void)in_sizes; (void)n_in; (void)out_size;
    const float* x    = (const float*)d_in[0];
    const float* bw   = (const float*)d_in[1];
    const float* jc   = (const float*)d_in[2];
    const float* bias = (const float*)d_in[3];
    float* out = (float*)d_out;

    {
        int n = OUT_F * KDIM;
        pack_w_kernel<<<(n + 255) / 256, 256>>>(bw, jc);
    }
    {
        int n = BATCH * IN_F;
        features_kernel<<<(n + 255) / 256, 256>>>(x);
    }
    {
        dim3 grid(OUT_F / BN, BATCH / BM);   // (8, 64)
        gemm_kernel<<<grid, 256>>>(bias, out);
    }
}

// round 4
// speedup vs baseline: 2.2544x; 2.2543x over previous
#include <cuda_runtime.h>
#include <cuda_fp16.h>
#include <cstdint>
#include <math.h>

#define BATCH 8192
#define IN_F  1024
#define OUT_F 1024
#define KDIM  6144
#define BM 128
#define BN 128
#define BK 32
#define KTILES (KDIM / BK)      // 192
#define ROWB 80                 // padded smem row bytes (40 halves)
#define STAGE_B (2 * BM * ROWB) // A tile + B tile = 20480
#define DYN_SMEM (3 * STAGE_B)  // 61440

__device__ __half g_F[(size_t)BATCH * KDIM];
__device__ __half g_W[(size_t)OUT_F * KDIM];
__device__ float  g_bias[OUT_F];

__device__ __forceinline__ uint32_t smem_u32(const void* p) {
    uint32_t a;
    asm("{ .reg .u64 t; cvta.to.shared.u64 t, %1; cvt.u32.u64 %0, t; }" : "=r"(a) : "l"(p));
    return a;
}
__device__ __forceinline__ void cp_async16(uint32_t s, const void* g) {
    asm volatile("cp.async.cg.shared.global [%0], [%1], 16;\n" :: "r"(s), "l"(g));
}
#define CP_COMMIT() asm volatile("cp.async.commit_group;\n" ::: "memory")
#define CP_WAIT(n)  asm volatile("cp.async.wait_group %0;\n" :: "n"(n) : "memory")

__device__ __forceinline__ void ldsm4(uint32_t r[4], uint32_t addr) {
    asm volatile("ldmatrix.sync.aligned.m8n8.x4.shared.b16 {%0,%1,%2,%3}, [%4];"
                 : "=r"(r[0]), "=r"(r[1]), "=r"(r[2]), "=r"(r[3]) : "r"(addr));
}
__device__ __forceinline__ void mma16816(float c[4], const uint32_t a[4],
                                         uint32_t b0, uint32_t b1) {
    asm volatile(
        "mma.sync.aligned.m16n8k16.row.col.f32.f16.f16.f32 "
        "{%0,%1,%2,%3}, {%4,%5,%6,%7}, {%8,%9}, {%0,%1,%2,%3};\n"
        : "+f"(c[0]), "+f"(c[1]), "+f"(c[2]), "+f"(c[3])
        : "r"(a[0]), "r"(a[1]), "r"(a[2]), "r"(a[3]), "r"(b0), "r"(b1));
}

// ---------------- kernel 1: pack W' (monomial basis, fp16) -----------------
__global__ void pack_w_kernel(const float* __restrict__ bw, const float* __restrict__ jc) {
    int idx = blockIdx.x * blockDim.x + threadIdx.x;   // o*1024 + i
    int o = idx >> 10, i = idx & 1023;
    const float* c = jc + (size_t)idx * 6;
    float c1 = c[1], c2 = c[2], c3 = c[3], c4 = c[4], c5 = c[5];
    float m1 = 2.0f * c1 - (15.0f / 14.0f) * c3 + (float)(2417.0 / 4158.0) * c5;
    float m2 = (16.0f / 15.0f) * c2 - (float)(988.0 / 945.0) * c4;
    float m3 = (4.0f / 7.0f) * c3 - (float)(5078.0 / 6237.0) * c5;
    float m4 = (float)(32.0 / 105.0) * c4;
    float m5 = (float)(16.0 / 99.0) * c5;
    __half* w = g_W + (size_t)o * KDIM + i;
    w[0]        = __float2half_rn(m1);
    w[IN_F]     = __float2half_rn(m2);
    w[2 * IN_F] = __float2half_rn(m3);
    w[3 * IN_F] = __float2half_rn(m4);
    w[4 * IN_F] = __float2half_rn(m5);
    w[5 * IN_F] = __float2half_rn(bw[idx]);
}

// ---------------- kernel 2: fold t^0 terms into bias -----------------------
__global__ void bias_kernel(const float* __restrict__ jc, const float* __restrict__ bias) {
    int o = blockIdx.x;
    const float* c = jc + (size_t)o * IN_F * 6;
    float s = 0.0f;
    for (int i = threadIdx.x; i < IN_F; i += 256)
        s += c[i * 6] - 0.4f * c[i * 6 + 2] + (float)(8.0 / 45.0) * c[i * 6 + 4];
    __shared__ float red[256];
    red[threadIdx.x] = s;
    __syncthreads();
    for (int st = 128; st > 0; st >>= 1) {
        if (threadIdx.x < st) red[threadIdx.x] += red[threadIdx.x + st];
        __syncthreads();
    }
    if (threadIdx.x == 0) g_bias[o] = bias[o] + red[0];
}

// ---------------- kernel 3: features [t,t2,t3,t4,t5,silu] fp16 -------------
__global__ void features_kernel(const float* __restrict__ x) {
    int idx = blockIdx.x * blockDim.x + threadIdx.x;   // BATCH*256 float4 ids
    int b = idx >> 8, i4 = idx & 255;
    float4 xv = reinterpret_cast<const float4*>(x)[idx];
    float in[4] = {xv.x, xv.y, xv.z, xv.w};
    __half o[6][4];
#pragma unroll
    for (int u = 0; u < 4; u++) {
        float xs = in[u];
        float t = tanhf(xs);
        float t2 = t * t, t3 = t2 * t, t4 = t2 * t2, t5 = t4 * t;
        o[0][u] = __float2half_rn(t);  o[1][u] = __float2half_rn(t2);
        o[2][u] = __float2half_rn(t3); o[3][u] = __float2half_rn(t4);
        o[4][u] = __float2half_rn(t5);
        o[5][u] = __float2half_rn(xs / (1.0f + expf(-xs)));
    }
    __half* base = g_F + (size_t)b * KDIM + i4 * 4;
#pragma unroll
    for (int j = 0; j < 6; j++)
        *reinterpret_cast<uint2*>(base + j * IN_F) = *reinterpret_cast<uint2*>(o[j]);
}

// ---------------- kernel 4: fp16 mma.sync GEMM -----------------------------
// out[b,o] = F[b,:] . W'[o,:] + bias'[o]
__global__ void __launch_bounds__(256, 2) gemm_kernel(float* __restrict__ out) {
    extern __shared__ __align__(16) char dsm[];
    const int tid = threadIdx.x, lane = tid & 31, wid = tid >> 5;
    const int wm = wid & 1, wn = wid >> 1;      // 2 x 4 warp grid, 64x32 tiles
    const int bn = blockIdx.x, bm = blockIdx.y;

    const __half* gA = g_F + (size_t)(bm * BM) * KDIM;
    const __half* gB = g_W + (size_t)(bn * BN) * KDIM;

    const uint32_t s0 = smem_u32(dsm);
    // loader: chunk = tid + 256*c ; row = chunk>>2 ; granule = chunk&3
    const int lr0 = tid >> 2, lg = tid & 3;
    // ldmatrix per-thread bases
    const uint32_t aAddr = s0 + (uint32_t)(wm * 64 + (lane & 15)) * ROWB + (lane >> 4) * 16;
    const uint32_t bAddr = s0 + (uint32_t)(BM * ROWB) +
                           (uint32_t)(wn * 32 + (lane & 15)) * ROWB + (lane >> 4) * 16;

    float acc[4][4][4];
#pragma unroll
    for (int i = 0; i < 4; i++)
#pragma unroll
        for (int j = 0; j < 4; j++)
#pragma unroll
            for (int r = 0; r < 4; r++) acc[i][j][r] = 0.0f;

#define FILL(s, kt) do { \
    uint32_t base_ = s0 + (s) * STAGE_B; \
    _Pragma("unroll") \
    for (int c_ = 0; c_ < 2; c_++) { \
        int row_ = lr0 + c_ * 64; \
        uint32_t off_ = (uint32_t)row_ * ROWB + lg * 16; \
        size_t gsrc_ = (size_t)row_ * KDIM + (size_t)(kt) * BK + lg * 8; \
        cp_async16(base_ + off_, gA + gsrc_); \
        cp_async16(base_ + BM * ROWB + off_, gB + gsrc_); \
    } \
    CP_COMMIT(); \
} while (0)

    FILL(0, 0);
    FILL(1, 1);

#pragma unroll 1
    for (int kt = 0; kt < KTILES; kt++) {
        const int s = kt - (kt / 3) * 3;
        if (kt == KTILES - 1) { CP_WAIT(0); } else { CP_WAIT(1); }
        __syncthreads();
        if (kt + 2 < KTILES) FILL((kt + 2) % 3, kt + 2);

        const uint32_t As = aAddr + s * STAGE_B;
        const uint32_t Bs = bAddr + s * STAGE_B;
#pragma unroll
        for (int kk = 0; kk < 2; kk++) {
            uint32_t a[4][4], b[2][4];
#pragma unroll
            for (int mf = 0; mf < 4; mf++)
                ldsm4(a[mf], As + mf * (16 * ROWB) + kk * 32);
#pragma unroll
            for (int nb = 0; nb < 2; nb++)
                ldsm4(b[nb], Bs + nb * (16 * ROWB) + kk * 32);
#pragma unroll
            for (int mf = 0; mf < 4; mf++)
#pragma unroll
                for (int nf = 0; nf < 4; nf++)
                    mma16816(acc[mf][nf], a[mf], b[nf >> 1][nf & 1], b[nf >> 1][(nf & 1) + 2]);
        }
    }

    // epilogue
#pragma unroll
    for (int mf = 0; mf < 4; mf++) {
        int r0 = bm * BM + wm * 64 + mf * 16 + (lane >> 2);
#pragma unroll
        for (int nf = 0; nf < 4; nf++) {
            int col = bn * BN + wn * 32 + nf * 8 + (lane & 3) * 2;
            float2 bv = *reinterpret_cast<const float2*>(&g_bias[col]);
            float2 v0 = make_float2(acc[mf][nf][0] + bv.x, acc[mf][nf][1] + bv.y);
            float2 v1 = make_float2(acc[mf][nf][2] + bv.x, acc[mf][nf][3] + bv.y);
            *reinterpret_cast<float2*>(out + (size_t)r0 * OUT_F + col)       = v0;
            *reinterpret_cast<float2*>(out + (size_t)(r0 + 8) * OUT_F + col) = v1;
        }
    }
}

// ---------------- launch ----------------------------------------------------
extern "C" void kernel_launch(void* const* d_in, const int* in_sizes, int n_in,
                              void* d_out, int out_size) {
    (void)in_sizes; (void)n_in; (void)out_size;
    const float* x    = (const float*)d_in[0];
    const float* bw   = (const float*)d_in[1];
    const float* jc   = (const float*)d_in[2];
    const float* bias = (const float*)d_in[3];
    float* out = (float*)d_out;

    cudaFuncSetAttribute(gemm_kernel, cudaFuncAttributeMaxDynamicSharedMemorySize, DYN_SMEM);

    pack_w_kernel<<<(OUT_F * IN_F) / 256, 256>>>(bw, jc);
    bias_kernel<<<OUT_F, 256>>>(jc, bias);
    features_kernel<<<(BATCH * IN_F / 4) / 256, 256>>>(x);
    dim3 grid(OUT_F / BN, BATCH / BM);   // (8, 64) = 512 CTAs
    gemm_kernel<<<grid, 256, DYN_SMEM>>>(out);
}

// round 5
// speedup vs baseline: 2.9140x; 1.2926x over previous
#include <cuda_runtime.h>
#include <cuda_fp16.h>
#include <cstdint>
#include <math.h>

#define BATCH 8192
#define IN_F  1024
#define OUT_F 1024
#define KDIM  6144
#define BM 128
#define BN 128
#define BK 64                     // halves per K-tile (128 bytes per row)
#define KTILES (KDIM / BK)        // 96
#define ROWB 128                  // smem row bytes, XOR-swizzled
#define STAGE_B (2 * BM * ROWB)   // 32768 (A 16KB + B 16KB)
#define NSTG 3
#define DYN_SMEM (NSTG * STAGE_B) // 98304

__device__ __half g_F[(size_t)BATCH * KDIM];
__device__ __half g_W[(size_t)OUT_F * KDIM];
__device__ float  g_bias[OUT_F];

__device__ __forceinline__ uint32_t smem_u32(const void* p) {
    uint32_t a;
    asm("{ .reg .u64 t; cvta.to.shared.u64 t, %1; cvt.u32.u64 %0, t; }" : "=r"(a) : "l"(p));
    return a;
}
__device__ __forceinline__ void cp_async16(uint32_t s, const void* g) {
    asm volatile("cp.async.cg.shared.global [%0], [%1], 16;\n" :: "r"(s), "l"(g));
}
#define CP_COMMIT() asm volatile("cp.async.commit_group;\n" ::: "memory")
#define CP_WAIT(n)  asm volatile("cp.async.wait_group %0;\n" :: "n"(n) : "memory")

__device__ __forceinline__ void ldsm4(uint32_t r[4], uint32_t addr) {
    asm volatile("ldmatrix.sync.aligned.m8n8.x4.shared.b16 {%0,%1,%2,%3}, [%4];"
                 : "=r"(r[0]), "=r"(r[1]), "=r"(r[2]), "=r"(r[3]) : "r"(addr));
}
__device__ __forceinline__ void mma16816(float c[4], const uint32_t a[4],
                                         uint32_t b0, uint32_t b1) {
    asm volatile(
        "mma.sync.aligned.m16n8k16.row.col.f32.f16.f16.f32 "
        "{%0,%1,%2,%3}, {%4,%5,%6,%7}, {%8,%9}, {%0,%1,%2,%3};\n"
        : "+f"(c[0]), "+f"(c[1]), "+f"(c[2]), "+f"(c[3])
        : "r"(a[0]), "r"(a[1]), "r"(a[2]), "r"(a[3]), "r"(b0), "r"(b1));
}

// ---------------- kernel 1: pack W' (monomial basis, fp16) -----------------
__global__ void pack_w_kernel(const float* __restrict__ bw, const float* __restrict__ jc) {
    int idx = blockIdx.x * blockDim.x + threadIdx.x;   // o*1024 + i
    int o = idx >> 10, i = idx & 1023;
    const float* c = jc + (size_t)idx * 6;
    float c1 = c[1], c2 = c[2], c3 = c[3], c4 = c[4], c5 = c[5];
    float m1 = 2.0f * c1 - (15.0f / 14.0f) * c3 + (float)(2417.0 / 4158.0) * c5;
    float m2 = (16.0f / 15.0f) * c2 - (float)(988.0 / 945.0) * c4;
    float m3 = (4.0f / 7.0f) * c3 - (float)(5078.0 / 6237.0) * c5;
    float m4 = (float)(32.0 / 105.0) * c4;
    float m5 = (float)(16.0 / 99.0) * c5;
    __half* w = g_W + (size_t)o * KDIM + i;
    w[0]        = __float2half_rn(m1);
    w[IN_F]     = __float2half_rn(m2);
    w[2 * IN_F] = __float2half_rn(m3);
    w[3 * IN_F] = __float2half_rn(m4);
    w[4 * IN_F] = __float2half_rn(m5);
    w[5 * IN_F] = __float2half_rn(bw[idx]);
}

// ---------------- kernel 2: fold t^0 terms into bias -----------------------
__global__ void bias_kernel(const float* __restrict__ jc, const float* __restrict__ bias) {
    int o = blockIdx.x;
    const float* c = jc + (size_t)o * IN_F * 6;
    float s = 0.0f;
    for (int i = threadIdx.x; i < IN_F; i += 256)
        s += c[i * 6] - 0.4f * c[i * 6 + 2] + (float)(8.0 / 45.0) * c[i * 6 + 4];
    __shared__ float red[256];
    red[threadIdx.x] = s;
    __syncthreads();
    for (int st = 128; st > 0; st >>= 1) {
        if (threadIdx.x < st) red[threadIdx.x] += red[threadIdx.x + st];
        __syncthreads();
    }
    if (threadIdx.x == 0) g_bias[o] = bias[o] + red[0];
}

// ---------------- kernel 3: features [t,t2,t3,t4,t5,silu] fp16 -------------
__global__ void features_kernel(const float* __restrict__ x) {
    int idx = blockIdx.x * blockDim.x + threadIdx.x;   // BATCH*256 float4 ids
    int b = idx >> 8, i4 = idx & 255;
    float4 xv = reinterpret_cast<const float4*>(x)[idx];
    float in[4] = {xv.x, xv.y, xv.z, xv.w};
    __half o[6][4];
#pragma unroll
    for (int u = 0; u < 4; u++) {
        float xs = in[u];
        float t = tanhf(xs);
        float t2 = t * t, t3 = t2 * t, t4 = t2 * t2, t5 = t4 * t;
        o[0][u] = __float2half_rn(t);  o[1][u] = __float2half_rn(t2);
        o[2][u] = __float2half_rn(t3); o[3][u] = __float2half_rn(t4);
        o[4][u] = __float2half_rn(t5);
        o[5][u] = __float2half_rn(xs / (1.0f + expf(-xs)));
    }
    __half* base = g_F + (size_t)b * KDIM + i4 * 4;
#pragma unroll
    for (int j = 0; j < 6; j++)
        *reinterpret_cast<uint2*>(base + j * IN_F) = *reinterpret_cast<uint2*>(o[j]);
}

// ---------------- kernel 4: fp16 mma.sync GEMM, swizzled, SW-pipelined ------
__global__ void __launch_bounds__(256, 2) gemm_kernel(float* __restrict__ out) {
    extern __shared__ __align__(16) char dsm[];
    const int tid = threadIdx.x, lane = tid & 31, wid = tid >> 5;
    const int wm = wid & 1, wn = wid >> 1;      // 2 x 4 warps, 64x32 tiles
    const int bn = blockIdx.x, bm = blockIdx.y;

    const __half* gA = g_F + (size_t)(bm * BM) * KDIM;
    const __half* gB = g_W + (size_t)(bn * BN) * KDIM;
    const uint32_t s0 = smem_u32(dsm);

    // ---- loader geometry: 4 chunk-pairs per thread per stage --------------
    // chunk = tid + 256*c ; row = chunk>>3 (0..127) ; ch = chunk&7
    // phys 16B slot = ch ^ (row&7)
    uint32_t sAoff[4]; size_t gOff[4];
#pragma unroll
    for (int c = 0; c < 4; c++) {
        int chunk = tid + 256 * c;
        int row = chunk >> 3, ch = chunk & 7;
        sAoff[c] = (uint32_t)(row * ROWB + ((ch ^ (row & 7)) << 4));
        gOff[c]  = (size_t)row * KDIM + ch * 8;
    }

    // ---- ldmatrix geometry -------------------------------------------------
    const int frow = lane & 15;                  // row within 16-row fragment
    const int hi   = lane >> 4;                  // 0: k-lo 16B, 1: k-hi 16B
    const int sw   = lane & 7;
    uint32_t xb[4];
#pragma unroll
    for (int kk = 0; kk < 4; kk++)
        xb[kk] = (uint32_t)(((2 * kk + hi) ^ sw) << 4);
    uint32_t aRow[4], bRow[2];
#pragma unroll
    for (int mf = 0; mf < 4; mf++)
        aRow[mf] = s0 + (uint32_t)((wm * 64 + mf * 16 + frow) * ROWB);
#pragma unroll
    for (int nb = 0; nb < 2; nb++)
        bRow[nb] = s0 + (uint32_t)(BM * ROWB + (wn * 32 + nb * 16 + frow) * ROWB);

    float acc[4][4][4];
#pragma unroll
    for (int i = 0; i < 4; i++)
#pragma unroll
        for (int j = 0; j < 4; j++)
#pragma unroll
            for (int r = 0; r < 4; r++) acc[i][j][r] = 0.0f;

#define FILL(s, kt) do { \
    uint32_t b_ = s0 + (s) * STAGE_B; \
    const __half* a0_ = gA + (size_t)(kt) * BK; \
    const __half* b0_ = gB + (size_t)(kt) * BK; \
    _Pragma("unroll") \
    for (int c_ = 0; c_ < 4; c_++) { \
        cp_async16(b_ + sAoff[c_], a0_ + gOff[c_]); \
        cp_async16(b_ + BM * ROWB + sAoff[c_], b0_ + gOff[c_]); \
    } \
    CP_COMMIT(); \
} while (0)

#define LDFRAGS(buf, kk, soff) do { \
    _Pragma("unroll") \
    for (int mf_ = 0; mf_ < 4; mf_++) ldsm4(af[buf][mf_], aRow[mf_] + (soff) + xb[kk]); \
    _Pragma("unroll") \
    for (int nb_ = 0; nb_ < 2; nb_++) ldsm4(bf[buf][nb_], bRow[nb_] + (soff) + xb[kk]); \
} while (0)

#define MMAS(buf) do { \
    _Pragma("unroll") \
    for (int mf_ = 0; mf_ < 4; mf_++) \
        _Pragma("unroll") \
        for (int nf_ = 0; nf_ < 4; nf_++) \
            mma16816(acc[mf_][nf_], af[buf][mf_], \
                     bf[buf][nf_ >> 1][nf_ & 1], bf[buf][nf_ >> 1][(nf_ & 1) + 2]); \
} while (0)

    uint32_t af[2][4][4], bf[2][2][4];

    FILL(0, 0);
    FILL(1, 1);

#pragma unroll 1
    for (int kt = 0; kt < KTILES; kt++) {
        if (kt == KTILES - 1) { CP_WAIT(0); } else { CP_WAIT(1); }
        __syncthreads();
        if (kt + 2 < KTILES) FILL((kt + 2) % NSTG, kt + 2);

        const uint32_t soff = (uint32_t)((kt % NSTG) * STAGE_B);
        LDFRAGS(0, 0, soff);
        LDFRAGS(1, 1, soff);
        MMAS(0);
        LDFRAGS(0, 2, soff);
        MMAS(1);
        LDFRAGS(1, 3, soff);
        MMAS(0);
        MMAS(1);
    }

    // ---- epilogue -----------------------------------------------------------
#pragma unroll
    for (int mf = 0; mf < 4; mf++) {
        int r0 = bm * BM + wm * 64 + mf * 16 + (lane >> 2);
#pragma unroll
        for (int nf = 0; nf < 4; nf++) {
            int col = bn * BN + wn * 32 + nf * 8 + (lane & 3) * 2;
            float2 bv = *reinterpret_cast<const float2*>(&g_bias[col]);
            float2 v0 = make_float2(acc[mf][nf][0] + bv.x, acc[mf][nf][1] + bv.y);
            float2 v1 = make_float2(acc[mf][nf][2] + bv.x, acc[mf][nf][3] + bv.y);
            *reinterpret_cast<float2*>(out + (size_t)r0 * OUT_F + col)       = v0;
            *reinterpret_cast<float2*>(out + (size_t)(r0 + 8) * OUT_F + col) = v1;
        }
    }
}

// ---------------- launch ----------------------------------------------------
extern "C" void kernel_launch(void* const* d_in, const int* in_sizes, int n_in,
                              void* d_out, int out_size) {
    (void)in_sizes; (void)n_in; (void)out_size;
    const float* x    = (const float*)d_in[0];
    const float* bw   = (const float*)d_in[1];
    const float* jc   = (const float*)d_in[2];
    const float* bias = (const float*)d_in[3];
    float* out = (float*)d_out;

    cudaFuncSetAttribute(gemm_kernel, cudaFuncAttributeMaxDynamicSharedMemorySize, DYN_SMEM);

    pack_w_kernel<<<(OUT_F * IN_F) / 256, 256>>>(bw, jc);
    bias_kernel<<<OUT_F, 256>>>(jc, bias);
    features_kernel<<<(BATCH * IN_F / 4) / 256, 256>>>(x);
    dim3 grid(OUT_F / BN, BATCH / BM);   // (8, 64) = 512 CTAs
    gemm_kernel<<<grid, 256, DYN_SMEM>>>(out);
}